// round 11
// baseline (speedup 1.0000x reference)
#include <cuda_runtime.h>
#include <math.h>

#define Bn 8
#define Sn 128
#define Nn 129
#define Dn 256
#define Hn 8

#define NEG_BIG 1.0e9f
#define NEG_INF (-3.402823466e38f)

// ------------------------- scratch (device globals; no allocs) ----------------
__device__ float g_wa [Dn*Dn];
__device__ float g_wb [Dn*Dn];
__device__ float g_ba [Dn];
__device__ float g_bb [Dn];
__device__ float g_a  [Bn*Sn*Dn];
__device__ float g_bm [Bn*Sn*Dn];
__device__ float g_v  [Bn*Nn*Dn];
__device__ float g_ctx[Bn*Nn*Dn];
__device__ float g_qs [Bn*Nn*Hn];
__device__ float g_ks [Bn*Nn*Hn];
__device__ float g_wqe[Dn*Hn];
__device__ float g_wke[Dn*Hn];
__device__ float g_u  [Dn*Hn];
__device__ float g_qb [Hn];
__device__ float g_kb [Hn];
__device__ float g_ub [Hn];
__device__ unsigned char g_na[Bn*Nn*Nn];

// ------------------------- 8-way head reduce (split butterfly) ---------------
__device__ __forceinline__ float reduce8(const float acc[8], int lane) {
    const unsigned FULL = 0xffffffffu;
    bool hi16 = (lane & 16) != 0;
    float s0 = hi16 ? acc[0] : acc[4];
    float s1 = hi16 ? acc[1] : acc[5];
    float s2 = hi16 ? acc[2] : acc[6];
    float s3 = hi16 ? acc[3] : acc[7];
    float r0 = __shfl_xor_sync(FULL, s0, 16);
    float r1 = __shfl_xor_sync(FULL, s1, 16);
    float r2 = __shfl_xor_sync(FULL, s2, 16);
    float r3 = __shfl_xor_sync(FULL, s3, 16);
    float v0 = (hi16 ? acc[4] : acc[0]) + r0;
    float v1 = (hi16 ? acc[5] : acc[1]) + r1;
    float v2 = (hi16 ? acc[6] : acc[2]) + r2;
    float v3 = (hi16 ? acc[7] : acc[3]) + r3;
    bool hi8 = (lane & 8) != 0;
    float t0 = hi8 ? v0 : v2;
    float t1 = hi8 ? v1 : v3;
    float q0 = __shfl_xor_sync(FULL, t0, 8);
    float q1 = __shfl_xor_sync(FULL, t1, 8);
    float w0 = (hi8 ? v2 : v0) + q0;
    float w1 = (hi8 ? v3 : v1) + q1;
    bool hi4 = (lane & 4) != 0;
    float u0 = hi4 ? w0 : w1;
    float p0 = __shfl_xor_sync(FULL, u0, 4);
    float x = (hi4 ? w1 : w0) + p0;
    x += __shfl_xor_sync(FULL, x, 2);
    x += __shfl_xor_sync(FULL, x, 1);
    return __shfl_sync(FULL, x, (lane & 7) << 2);
}

// ------------------------- fp32 GEMM tile (device fn, dyn smem) --------------
// C[bm:bm+64, bn:bn+64] = A(MxK=256) @ W(256x256) + bias
#define TM 64
#define TN 64
#define TK 16
#define NIT (Dn/TK)
#define GEMM_SMEM ((2*TK*(TM+4) + 2*TK*TN)*4)

__device__ __forceinline__ void gemm_tile(const float* __restrict__ A, const float* __restrict__ W,
                                          const float* __restrict__ bias, float* __restrict__ C,
                                          int M, int bm, int bn, char* raw) {
    float (*As)[TM+4] = (float (*)[TM+4])raw;                         // [2*TK][TM+4]
    float (*Ws)[TN]   = (float (*)[TN])(raw + 2*TK*(TM+4)*4);         // [2*TK][TN]
    int tid = threadIdx.x;

    int arow = tid >> 2;            // 0..63
    int ak   = (tid & 3) << 2;      // 0,4,8,12
    int wrow = tid >> 4;            // 0..15
    int wc   = (tid & 15) << 2;     // 0..60

    const float* Aptr = A + (size_t)(bm + arow) * Dn + ak;
    const float* Wptr = W + (size_t)wrow * Dn + bn + wc;
    bool arow_ok = (bm + arow) < M;

    float4 av = arow_ok ? *(const float4*)Aptr : make_float4(0.f,0.f,0.f,0.f);
    float4 wv = *(const float4*)Wptr;
    As[ak+0][arow]=av.x; As[ak+1][arow]=av.y;
    As[ak+2][arow]=av.z; As[ak+3][arow]=av.w;
    *(float4*)&Ws[wrow][wc] = wv;
    __syncthreads();

    int tx = tid & 15, ty = tid >> 4;
    float acc[4][4];
    #pragma unroll
    for (int r = 0; r < 4; r++)
        #pragma unroll
        for (int c = 0; c < 4; c++) acc[r][c] = 0.f;

    #pragma unroll 2
    for (int it = 0; it < NIT; it++) {
        int cb = (it & 1) * TK;
        if (it + 1 < NIT) {
            av = arow_ok ? *(const float4*)(Aptr + (it+1)*TK) : make_float4(0.f,0.f,0.f,0.f);
            wv = *(const float4*)(Wptr + (size_t)(it+1)*TK*Dn);
        }
        #pragma unroll
        for (int k = 0; k < TK; k++) {
            float4 ra = *(const float4*)&As[cb + k][ty << 2];
            float4 rb = *(const float4*)&Ws[cb + k][tx << 2];
            acc[0][0]=fmaf(ra.x,rb.x,acc[0][0]); acc[0][1]=fmaf(ra.x,rb.y,acc[0][1]);
            acc[0][2]=fmaf(ra.x,rb.z,acc[0][2]); acc[0][3]=fmaf(ra.x,rb.w,acc[0][3]);
            acc[1][0]=fmaf(ra.y,rb.x,acc[1][0]); acc[1][1]=fmaf(ra.y,rb.y,acc[1][1]);
            acc[1][2]=fmaf(ra.y,rb.z,acc[1][2]); acc[1][3]=fmaf(ra.y,rb.w,acc[1][3]);
            acc[2][0]=fmaf(ra.z,rb.x,acc[2][0]); acc[2][1]=fmaf(ra.z,rb.y,acc[2][1]);
            acc[2][2]=fmaf(ra.z,rb.z,acc[2][2]); acc[2][3]=fmaf(ra.z,rb.w,acc[2][3]);
            acc[3][0]=fmaf(ra.w,rb.x,acc[3][0]); acc[3][1]=fmaf(ra.w,rb.y,acc[3][1]);
            acc[3][2]=fmaf(ra.w,rb.z,acc[3][2]); acc[3][3]=fmaf(ra.w,rb.w,acc[3][3]);
        }
        if (it + 1 < NIT) {
            int nb = (cb ^ TK);
            As[nb + ak+0][arow]=av.x; As[nb + ak+1][arow]=av.y;
            As[nb + ak+2][arow]=av.z; As[nb + ak+3][arow]=av.w;
            *(float4*)&Ws[nb + wrow][wc] = wv;
        }
        __syncthreads();
    }

    float4 bvec = make_float4(0.f,0.f,0.f,0.f);
    if (bias) bvec = *(const float4*)&bias[bn + (tx << 2)];
    #pragma unroll
    for (int r = 0; r < 4; r++) {
        int row = bm + (ty << 2) + r;
        if (row < M) {
            float4 o;
            o.x = acc[r][0] + bvec.x; o.y = acc[r][1] + bvec.y;
            o.z = acc[r][2] + bvec.z; o.w = acc[r][3] + bvec.w;
            *(float4*)&C[(size_t)row * Dn + bn + (tx << 2)] = o;
        }
    }
}

// ------------------------- weight fold: warp per row -------------------------
__device__ __forceinline__ void fold_row(const float* __restrict__ src,
                                         const float* __restrict__ wv,
                                         float* __restrict__ dst, int lane) {
    float w = wv[lane];
    float acc[8];
    #pragma unroll
    for (int h = 0; h < 8; h++) acc[h] = src[h*32 + lane] * w;
    float r = reduce8(acc, lane);
    if (lane < 8) dst[lane] = r;
}

__device__ void fold_block(int fb, const float* __restrict__ Wq, const float* __restrict__ bq,
                           const float* __restrict__ Wk, const float* __restrict__ bk,
                           const float* __restrict__ We2, const float* __restrict__ be2,
                           const float* __restrict__ wattn) {
    int warp = threadIdx.x >> 5, lane = threadIdx.x & 31;
    int wg = fb * 8 + warp;               // 0..95
    const float* wq = wattn;
    const float* wk = wattn + 32;
    const float* we = wattn + 64;
    #pragma unroll
    for (int rr = 0; rr < 8; rr++) {
        int row = wg + 96*rr;             // 0..767
        int mat = row >> 8, d = row & 255;
        if (mat == 0)      fold_row(Wq  + (size_t)d*Dn, wq, g_wqe + d*Hn, lane);
        else if (mat == 1) fold_row(Wk  + (size_t)d*Dn, wk, g_wke + d*Hn, lane);
        else               fold_row(We2 + (size_t)d*Dn, we, g_u   + d*Hn, lane);
    }
    if (wg == 0)      fold_row(bq,  wq, g_qb, lane);
    else if (wg == 1) fold_row(bk,  wk, g_kb, lane);
    else if (wg == 2) fold_row(be2, we, g_ub, lane);
}

// ------------------------- bias fold: ba = b_gt@W_e1a + b_e1, bb = b_gt@W_e1b
__device__ void bias_fold(const float* __restrict__ b_gt, const float* __restrict__ W_e1,
                          const float* __restrict__ b_e1) {
    int j = threadIdx.x;                  // 256 threads, column j
    float sa = 0.f, sb = 0.f;
    for (int k = 0; k < Dn; k++) {
        float g = b_gt[k];
        sa = fmaf(g, W_e1[(size_t)k*Dn + j], sa);
        sb = fmaf(g, W_e1[(size_t)(Dn + k)*Dn + j], sb);
    }
    g_ba[j] = sa + b_e1[j];
    g_bb[j] = sb;
}

// ------------------------- adjacency sign mask tile --------------------------
#define NA_PAD 264
#define NA_SMEM (2*32*NA_PAD*4)
__device__ void na_tile(const float* __restrict__ nv, int b, int it, int jt, char* raw) {
    float* sI = (float*)raw;
    float* sJ = sI + 32*NA_PAD;
    int tid = threadIdx.x;
    for (int idx = tid; idx < 32*64; idx += 256) {
        int row = idx >> 6;
        int c4  = (idx & 63) * 4;
        *(float4*)&sI[row*NA_PAD + c4] = *(const float4*)&nv[(size_t)(b*Nn + 1 + it*32 + row)*Dn + c4];
        *(float4*)&sJ[row*NA_PAD + c4] = *(const float4*)&nv[(size_t)(b*Nn + 1 + jt*32 + row)*Dn + c4];
    }
    __syncthreads();
    int tx = tid & 15, ty = tid >> 4;
    int i0 = ty*2, j0 = tx*2;
    const float* pi0 = sI + i0*NA_PAD;
    const float* pi1 = pi0 + NA_PAD;
    const float* pj0 = sJ + j0*NA_PAD;
    const float* pj1 = pj0 + NA_PAD;
    float a00 = 0.f, a01 = 0.f, a10 = 0.f, a11 = 0.f;
    for (int d = 0; d < Dn; d += 4) {
        float4 x0 = *(const float4*)(pi0 + d);
        float4 x1 = *(const float4*)(pi1 + d);
        float4 y0 = *(const float4*)(pj0 + d);
        float4 y1 = *(const float4*)(pj1 + d);
        a00 += x0.x*y0.x + x0.y*y0.y + x0.z*y0.z + x0.w*y0.w;
        a01 += x0.x*y1.x + x0.y*y1.y + x0.z*y1.z + x0.w*y1.w;
        a10 += x1.x*y0.x + x1.y*y0.y + x1.z*y0.z + x1.w*y0.w;
        a11 += x1.x*y1.x + x1.y*y1.y + x1.z*y1.z + x1.w*y1.w;
    }
    int gi = it*32 + i0, gj = jt*32 + j0;
    g_na[(size_t)(b*Nn + 1+gi  )*Nn + 1+gj  ] = (a00 > 0.f) && (gi   != gj  );
    g_na[(size_t)(b*Nn + 1+gi  )*Nn + 1+gj+1] = (a01 > 0.f) && (gi   != gj+1);
    g_na[(size_t)(b*Nn + 1+gi+1)*Nn + 1+gj  ] = (a10 > 0.f) && (gi+1 != gj  );
    g_na[(size_t)(b*Nn + 1+gi+1)*Nn + 1+gj+1] = (a11 > 0.f) && (gi+1 != gj+1);
}

// ------------------------- qs/ks tile: warp per row --------------------------
__device__ void qsks_tile(const float* __restrict__ nv, int qb, char* raw) {
    float* swq = (float*)raw;
    float* swk = swq + Dn*Hn;
    int tid = threadIdx.x;
    for (int i = tid; i < Dn*Hn; i += 256) { swq[i] = g_wqe[i]; swk[i] = g_wke[i]; }
    __syncthreads();
    int warp = tid >> 5, lane = tid & 31;
    int r = qb * 8 + warp;
    if (r >= Bn*Nn) return;
    const float* row = nv + (size_t)r * Dn;
    int dlo = lane*4, dhi = 128 + lane*4;
    float4 x0 = *(const float4*)(row + dlo);
    float4 x1 = *(const float4*)(row + dhi);
    float xv[8] = {x0.x,x0.y,x0.z,x0.w,x1.x,x1.y,x1.z,x1.w};
    float aq[8] = {0,0,0,0,0,0,0,0};
    float ak[8] = {0,0,0,0,0,0,0,0};
    #pragma unroll
    for (int rr = 0; rr < 8; rr++) {
        int d = (rr < 4) ? (dlo + rr) : (dhi + rr - 4);
        float4 wqa = *(const float4*)&swq[d*Hn];
        float4 wqb = *(const float4*)&swq[d*Hn + 4];
        float4 wka = *(const float4*)&swk[d*Hn];
        float4 wkb = *(const float4*)&swk[d*Hn + 4];
        float x = xv[rr];
        aq[0]=fmaf(x,wqa.x,aq[0]); aq[1]=fmaf(x,wqa.y,aq[1]);
        aq[2]=fmaf(x,wqa.z,aq[2]); aq[3]=fmaf(x,wqa.w,aq[3]);
        aq[4]=fmaf(x,wqb.x,aq[4]); aq[5]=fmaf(x,wqb.y,aq[5]);
        aq[6]=fmaf(x,wqb.z,aq[6]); aq[7]=fmaf(x,wqb.w,aq[7]);
        ak[0]=fmaf(x,wka.x,ak[0]); ak[1]=fmaf(x,wka.y,ak[1]);
        ak[2]=fmaf(x,wka.z,ak[2]); ak[3]=fmaf(x,wka.w,ak[3]);
        ak[4]=fmaf(x,wkb.x,ak[4]); ak[5]=fmaf(x,wkb.y,ak[5]);
        ak[6]=fmaf(x,wkb.z,ak[6]); ak[7]=fmaf(x,wkb.w,ak[7]);
    }
    float rq = reduce8(aq, lane);
    float rk = reduce8(ak, lane);
    if (lane < Hn) {
        g_qs[r*Hn + lane] = rq + g_qb[lane];
        g_ks[r*Hn + lane] = rk + g_kb[lane];
    }
}

// ------------------------- per-edge LN + relu + 8-head dot -------------------
__device__ __forceinline__ float edge_ln_dot8(const float x[8], const float gg[8],
                                              const float bbv[8], const float ur[8][8],
                                              int lane) {
    float s = 0.f, ss = 0.f;
    #pragma unroll
    for (int r = 0; r < 8; r++) { s += x[r]; ss = fmaf(x[r], x[r], ss); }
    #pragma unroll
    for (int off = 16; off; off >>= 1) {
        s  += __shfl_xor_sync(0xffffffffu, s,  off);
        ss += __shfl_xor_sync(0xffffffffu, ss, off);
    }
    float mu  = s  * (1.f/256.f);
    float var = ss * (1.f/256.f) - mu*mu;
    float rs  = 1.f / sqrtf(var + 1e-5f);
    float nm  = -mu * rs;
    float acc[8] = {0.f,0.f,0.f,0.f,0.f,0.f,0.f,0.f};
    #pragma unroll
    for (int r = 0; r < 8; r++) {
        float t = fmaf(x[r], rs, nm);
        t = fmaf(t, gg[r], bbv[r]);
        t = fmaxf(t, 0.f);
        #pragma unroll
        for (int h = 0; h < Hn; h++) acc[h] = fmaf(t, ur[r][h], acc[h]);
    }
    return reduce8(acc, lane);
}

__device__ __forceinline__ void edge_preload(int lane, const float* __restrict__ ln_g,
                                             const float* __restrict__ ln_b,
                                             float gg[8], float bbv[8], float ur[8][8]) {
    int dlo = lane*4, dhi = 128 + lane*4;
    #pragma unroll
    for (int r = 0; r < 4; r++) {
        gg [r]   = ln_g[dlo+r]; bbv[r]   = ln_b[dlo+r];
        gg [4+r] = ln_g[dhi+r]; bbv[4+r] = ln_b[dhi+r];
        #pragma unroll
        for (int h = 0; h < Hn; h++) {
            ur[r][h]   = g_u[(dlo+r)*Hn + h];
            ur[4+r][h] = g_u[(dhi+r)*Hn + h];
        }
    }
}

// ------------------------- edges for row i==0 --------------------------------
__device__ void edge_row0(int b, const float* __restrict__ ln_g, const float* __restrict__ ln_b,
                          float battn, float* __restrict__ scores) {
    int tid = threadIdx.x, warp = tid >> 5, lane = tid & 31;
    float gg[8], bbv[8], ur[8][8];
    edge_preload(lane, ln_g, ln_b, gg, bbv, ur);
    float ub = (lane < Hn) ? g_ub[lane] : 0.f;
    int dlo = lane*4, dhi = 128 + lane*4;

    for (int j = warp; j <= 128; j += 8) {
        if (j == 0) {
            if (lane < Hn) {
                float sc = g_qs[(b*Nn+0)*Hn + lane] + g_ks[(b*Nn+0)*Hn + lane] + battn - NEG_BIG;
                scores[((size_t)(b*Hn + lane)*Nn + 0)*Nn + 0] = sc;
            }
            continue;
        }
        int s = j - 1;
        const float* ar = g_a  + (size_t)(b*Sn + s)*Dn;
        const float* br = g_bm + (size_t)(b*Sn + s)*Dn;
        float4 a0 = *(const float4*)(ar + dlo), b0 = *(const float4*)(br + dlo);
        float4 a1 = *(const float4*)(ar + dhi), b1 = *(const float4*)(br + dhi);
        float x[8];
        x[0]=a0.x+b0.x; x[1]=a0.y+b0.y; x[2]=a0.z+b0.z; x[3]=a0.w+b0.w;
        x[4]=a1.x+b1.x; x[5]=a1.y+b1.y; x[6]=a1.z+b1.z; x[7]=a1.w+b1.w;
        float edot = edge_ln_dot8(x, gg, bbv, ur, lane);
        if (lane < Hn) {
            float sc = g_qs[(b*Nn+0)*Hn + lane] + g_ks[(b*Nn+j)*Hn + lane] + battn
                     + edot + ub;
            scores[((size_t)(b*Hn + lane)*Nn + 0)*Nn + j] = sc;
        }
    }
}

// ------------------------- main edge tile (i in 1..128) ----------------------
// smem: bT[32*256] qsT[32*8] ksT[32*8] scT[8*1025] naT[1024]
#define SCT_PITCH 1025
#define EDGE_SMEM ((32*256 + 32*8 + 32*8 + 8*SCT_PITCH)*4 + 1024)
__device__ void edge_main(int b, int it, int jt,
                          const float* __restrict__ ln_g, const float* __restrict__ ln_b,
                          float battn, float* __restrict__ scores, char* raw) {
    float* bT  = (float*)raw;
    float* qsT = bT + 32*256;
    float* ksT = qsT + 32*8;
    float* scT = ksT + 32*8;
    unsigned char* naT = (unsigned char*)(scT + 8*SCT_PITCH);

    int tid = threadIdx.x, warp = tid >> 5, lane = tid & 31;

    for (int idx = tid; idx < 32*64; idx += 256) {
        int row = idx >> 6;
        int c4  = (idx & 63) * 4;
        int j = jt*32 + row;
        float4 bv = make_float4(0.f,0.f,0.f,0.f);
        if (j >= 1 && j <= 128)
            bv = *(const float4*)&g_bm[(size_t)(b*Sn + j - 1)*Dn + c4];
        *(float4*)&bT[row*256 + c4] = bv;
    }
    {
        int r = tid >> 3, h = tid & 7;
        int i = 1 + it*32 + r;
        qsT[tid] = g_qs[(size_t)(b*Nn + i)*Hn + h];
        int j = jt*32 + r;
        ksT[tid] = (j <= 128) ? g_ks[(size_t)(b*Nn + j)*Hn + h] : 0.f;
    }
    for (int idx = tid; idx < 1024; idx += 256) {
        int ei = idx >> 5, ej = idx & 31;
        int j = jt*32 + ej;
        int i = 1 + it*32 + ei;
        naT[idx] = (j >= 1 && j <= 128) ? g_na[(size_t)(b*Nn + i)*Nn + j] : 0;
    }

    float gg[8], bbv[8], ur[8][8];
    edge_preload(lane, ln_g, ln_b, gg, bbv, ur);
    float ub = (lane < Hn) ? g_ub[lane] : 0.f;
    __syncthreads();

    #pragma unroll
    for (int eib = 0; eib < 4; eib++) {
        int ei = warp + eib*8;                   // 0..31
        const float* ar = g_a + (size_t)(b*Sn + it*32 + ei)*Dn;
        float4 a0 = *(const float4*)(ar + lane*4);
        float4 a1 = *(const float4*)(ar + 128 + lane*4);
        for (int ej = 0; ej < 32; ej++) {
            int j = jt*32 + ej;
            if (j > 128) continue;
            int slot = ei*32 + ej;
            unsigned char mk = naT[slot];
            float edot = 0.f;
            if (mk) {
                const float* brow = bT + ej*256;
                float4 b0 = *(const float4*)(brow + lane*4);
                float4 b1 = *(const float4*)(brow + 128 + lane*4);
                float x[8];
                x[0]=a0.x+b0.x; x[1]=a0.y+b0.y; x[2]=a0.z+b0.z; x[3]=a0.w+b0.w;
                x[4]=a1.x+b1.x; x[5]=a1.y+b1.y; x[6]=a1.z+b1.z; x[7]=a1.w+b1.w;
                edot = edge_ln_dot8(x, gg, bbv, ur, lane);
            }
            if (lane < Hn) {
                float sc = qsT[ei*8 + lane] + ksT[ej*8 + lane] + battn;
                sc = mk ? (sc + edot + ub) : (sc - NEG_BIG);
                scT[lane*SCT_PITCH + slot] = sc;
            }
        }
    }
    __syncthreads();
    for (int idx = tid; idx < 8192; idx += 256) {
        int h    = idx >> 10;
        int slot = idx & 1023;
        int ei   = slot >> 5;
        int ej   = slot & 31;
        int j = jt*32 + ej;
        if (j <= 128) {
            int i = 1 + it*32 + ei;
            scores[((size_t)(b*Hn + h)*Nn + i)*Nn + j] = scT[h*SCT_PITCH + slot];
        }
    }
}

// ========================= phase mega-kernels ================================

// P0: Wa GEMM (16) | Wb GEMM (16) | v GEMM (68) | na (128) | fold (12) | bias (1) = 241
__global__ void __launch_bounds__(256)
mega0_kernel(const float* __restrict__ W_gt, const float* __restrict__ W_e1,
             const float* __restrict__ b_gt, const float* __restrict__ b_e1,
             const float* __restrict__ nv,   const float* __restrict__ W_v, const float* __restrict__ b_v,
             const float* __restrict__ W_q,  const float* __restrict__ b_q,
             const float* __restrict__ W_k,  const float* __restrict__ b_k,
             const float* __restrict__ We2,  const float* __restrict__ be2,
             const float* __restrict__ wattn) {
    extern __shared__ char raw[];
    int id = blockIdx.x;
    if (id < 16)  { gemm_tile(W_gt, W_e1, nullptr, g_wa, Dn, (id>>2)*TM, (id&3)*TN, raw); return; }
    id -= 16;
    if (id < 16)  { gemm_tile(W_gt, W_e1 + Dn*Dn, nullptr, g_wb, Dn, (id>>2)*TM, (id&3)*TN, raw); return; }
    id -= 16;
    if (id < 68)  { gemm_tile(nv, W_v, b_v, g_v, Bn*Nn, (id>>2)*TM, (id&3)*TN, raw); return; }
    id -= 68;
    if (id < 128) { na_tile(nv, id >> 4, (id >> 2) & 3, id & 3, raw); return; }
    id -= 128;
    if (id < 12)  { fold_block(id, W_q, b_q, W_k, b_k, We2, be2, wattn); return; }
    bias_fold(b_gt, W_e1, b_e1);
}

// P1: a GEMM (64) | b GEMM (64) | qsks (129) = 257
__global__ void __launch_bounds__(256)
mega1_kernel(const float* __restrict__ desc, const float* __restrict__ nv) {
    extern __shared__ char raw[];
    int id = blockIdx.x;
    if (id < 64)  { gemm_tile(desc, g_wa, g_ba, g_a, Bn*Sn, (id>>2)*TM, (id&3)*TN, raw); return; }
    id -= 64;
    if (id < 64)  { gemm_tile(desc, g_wb, g_bb, g_bm, Bn*Sn, (id>>2)*TM, (id&3)*TN, raw); return; }
    id -= 64;
    qsks_tile(nv, id, raw);
}

// P2: edge_row0 (8) | edge_main (160)  = 168 blocks
__global__ void __launch_bounds__(256)
mega3_kernel(const float* __restrict__ ln_g, const float* __restrict__ ln_b,
             const float* __restrict__ p_battn, float* __restrict__ scores) {
    extern __shared__ char raw[];
    float battn = *p_battn;
    int id = blockIdx.x;
    if (id < 8) { edge_row0(id, ln_g, ln_b, battn, scores); return; }
    id -= 8;
    int b = id / 20, rem = id % 20;
    edge_main(b, rem / 5, rem % 5, ln_g, ln_b, battn, scores, raw);
}

// P3: fused softmax + ctx, dual-row per warp (grid 64 x 8)
__device__ __forceinline__ void softmax_row_load(const float* __restrict__ p, int lane,
                                                 float v[5], float& m) {
    m = NEG_INF;
    #pragma unroll
    for (int k = 0; k < 5; k++) {
        int j = k*32 + lane;
        v[k] = (j < Nn) ? p[j] : NEG_INF;
        m = fmaxf(m, v[k]);
    }
}

__global__ void __launch_bounds__(256) softmax_ctx_kernel(float* __restrict__ scores) {
    __shared__ float vT[Nn][33];
    int bh = blockIdx.x;
    int b = bh >> 3, h = bh & 7;
    int tid = threadIdx.x, warp = tid >> 5, lane = tid & 31;
    for (int idx = tid; idx < Nn*32; idx += 256) {
        int j = idx >> 5, c = idx & 31;
        vT[j][c] = g_v[(size_t)(b*Nn + j)*Dn + h*32 + c];
    }
    __syncthreads();
    const unsigned FULL = 0xffffffffu;

    int start = blockIdx.y*8 + warp;     // 0..63
    int r1 = start, r2 = start + 64;
    int nrows = (start == 0) ? 3 : 2;    // row 128 tacked onto warp 0 of by 0

    // --- dual-row softmax + ctx for r1, r2 (interleaved for ILP) ---
    {
        float* p1 = scores + ((size_t)(b*Hn + h)*Nn + r1)*Nn;
        float* p2 = scores + ((size_t)(b*Hn + h)*Nn + r2)*Nn;
        float va[5], vb[5], m1, m2;
        softmax_row_load(p1, lane, va, m1);
        softmax_row_load(p2, lane, vb, m2);
        #pragma unroll
        for (int off = 16; off; off >>= 1) {
            m1 = fmaxf(m1, __shfl_xor_sync(FULL, m1, off));
            m2 = fmaxf(m2, __shfl_xor_sync(FULL, m2, off));
        }
        float s1 = 0.f, s2 = 0.f;
        #pragma unroll
        for (int k = 0; k < 5; k++) {
            int j = k*32 + lane;
            if (j < Nn) { va[k] = expf(va[k] - m1); s1 += va[k];
                          vb[k] = expf(vb[k] - m2); s2 += vb[k]; }
            else        { va[k] = 0.f; vb[k] = 0.f; }
        }
        #pragma unroll
        for (int off = 16; off; off >>= 1) {
            s1 += __shfl_xor_sync(FULL, s1, off);
            s2 += __shfl_xor_sync(FULL, s2, off);
        }
        float i1 = 1.f / s1, i2 = 1.f / s2;
        #pragma unroll
        for (int k = 0; k < 5; k++) {
            int j = k*32 + lane;
            va[k] *= i1; vb[k] *= i2;
            if (j < Nn) { p1[j] = va[k]; p2[j] = vb[k]; }
        }
        float a0c=0.f,a1c=0.f,a2c=0.f,a3c=0.f;
        float b0c=0.f,b1c=0.f,b2c=0.f,b3c=0.f;
        #pragma unroll
        for (int jj = 0; jj < 128; jj += 4) {
            float ra = va[jj >> 5];
            float rb = vb[jj >> 5];
            float xa0 = __shfl_sync(FULL, ra, (jj+0) & 31);
            float xb0 = __shfl_sync(FULL, rb, (jj+0) & 31);
            float xa1 = __shfl_sync(FULL, ra, (jj+1) & 31);
            float xb1 = __shfl_sync(FULL, rb, (jj+1) & 31);
            float xa2 = __shfl_sync(FULL, ra, (jj+2) & 31);
            float xb2 = __shfl_sync(FULL, rb, (jj+2) & 31);
            float xa3 = __shfl_sync(FULL, ra, (jj+3) & 31);
            float xb3 = __shfl_sync(FULL, rb, (jj+3) & 31);
            float t0 = vT[jj+0][lane], t1 = vT[jj+1][lane];
            float t2 = vT[jj+2][lane], t3 = vT[jj+3][lane];
            a0c = fmaf(xa0, t0, a0c);  b0c = fmaf(xb0, t0, b0c);
            a1c = fmaf(xa1, t1, a1c);  b1c = fmaf(xb1, t1, b1c);
            a2c = fmaf(xa2, t2, a2c);  b2c = fmaf(xb2, t2, b2c);
            a3c = fmaf(xa3, t3, a3c);  b3c = fmaf(xb3, t3, b3c);
        }
        float tl = vT[128][lane];
        float xaL = __shfl_sync(FULL, va[4], 0);
        float xbL = __shfl_sync(FULL, vb[4], 0);
        a0c = fmaf(xaL, tl, a0c);
        b0c = fmaf(xbL, tl, b0c);
        g_ctx[(size_t)(b*Nn + r1)*Dn + h*32 + lane] = (a0c + a1c) + (a2c + a3c);
        g_ctx[(size_t)(b*Nn + r2)*Dn + h*32 + lane] = (b0c + b1c) + (b2c + b3c);
    }

    // --- single row 128 (only warp with start==0) ---
    if (nrows == 3) {
        int i = 128;
        float* prow = scores + ((size_t)(b*Hn + h)*Nn + i)*Nn;
        float v[5], m;
        softmax_row_load(prow, lane, v, m);
        #pragma unroll
        for (int off = 16; off; off >>= 1) m = fmaxf(m, __shfl_xor_sync(FULL, m, off));
        float sum = 0.f;
        #pragma unroll
        for (int k = 0; k < 5; k++) {
            int j = k*32 + lane;
            if (j < Nn) { v[k] = expf(v[k] - m); sum += v[k]; }
            else        { v[k] = 0.f; }
        }
        #pragma unroll
        for (int off = 16; off; off >>= 1) sum += __shfl_xor_sync(FULL, sum, off);
        float inv = 1.f / sum;
        #pragma unroll
        for (int k = 0; k < 5; k++) {
            int j = k*32 + lane;
            v[k] *= inv;
            if (j < Nn) prow[j] = v[k];
        }
        float acc0 = 0.f, acc1 = 0.f, acc2 = 0.f, acc3 = 0.f;
        #pragma unroll
        for (int jj = 0; jj < 128; jj += 4) {
            float r  = v[jj >> 5];
            float x0 = __shfl_sync(FULL, r, (jj+0) & 31);
            float x1 = __shfl_sync(FULL, r, (jj+1) & 31);
            float x2 = __shfl_sync(FULL, r, (jj+2) & 31);
            float x3 = __shfl_sync(FULL, r, (jj+3) & 31);
            acc0 = fmaf(x0, vT[jj+0][lane], acc0);
            acc1 = fmaf(x1, vT[jj+1][lane], acc1);
            acc2 = fmaf(x2, vT[jj+2][lane], acc2);
            acc3 = fmaf(x3, vT[jj+3][lane], acc3);
        }
        float aLast = __shfl_sync(FULL, v[4], 0);
        acc0 = fmaf(aLast, vT[128][lane], acc0);
        g_ctx[(size_t)(b*Nn + i)*Dn + h*32 + lane] = (acc0 + acc1) + (acc2 + acc3);
    }
}

// P4: ctx -> out GEMM (68 blocks)
__global__ void __launch_bounds__(256)
gemm_out_kernel(const float* __restrict__ W_o, const float* __restrict__ b_o,
                float* __restrict__ outp) {
    extern __shared__ char raw[];
    int id = blockIdx.x;
    gemm_tile(g_ctx, W_o, b_o, outp, Bn*Nn, (id>>2)*TM, (id&3)*TN, raw);
}

// ------------------------- launch --------------------------------------------
extern "C" void kernel_launch(void* const* d_in, const int* in_sizes, int n_in,
                              void* d_out, int out_size) {
    const float* desc   = (const float*)d_in[0];
    const float* nv     = (const float*)d_in[1];
    const float* W_gt   = (const float*)d_in[2];
    const float* b_gt   = (const float*)d_in[3];
    // d_in[4] = topo_bias: irrelevant to forward value (sigmoid>0 always)
    const float* W_q    = (const float*)d_in[5];
    const float* b_q    = (const float*)d_in[6];
    const float* W_k    = (const float*)d_in[7];
    const float* b_k    = (const float*)d_in[8];
    const float* W_v    = (const float*)d_in[9];
    const float* b_v    = (const float*)d_in[10];
    const float* W_e1   = (const float*)d_in[11];
    const float* b_e1   = (const float*)d_in[12];
    const float* ln_g   = (const float*)d_in[13];
    const float* ln_b   = (const float*)d_in[14];
    const float* W_e2   = (const float*)d_in[15];
    const float* b_e2   = (const float*)d_in[16];
    const float* w_attn = (const float*)d_in[17];
    const float* b_attn = (const float*)d_in[18];
    const float* W_o    = (const float*)d_in[19];
    const float* b_o    = (const float*)d_in[20];

    float* outp   = (float*)d_out;
    float* scores = outp + Bn*Nn*Dn;     // attn region of output, used in place

    cudaFuncSetAttribute(mega0_kernel, cudaFuncAttributeMaxDynamicSharedMemorySize, NA_SMEM);
    cudaFuncSetAttribute(mega3_kernel, cudaFuncAttributeMaxDynamicSharedMemorySize, EDGE_SMEM);

    mega0_kernel<<<241, 256, NA_SMEM>>>(W_gt, W_e1, b_gt, b_e1, nv, W_v, b_v,
                                        W_q, b_q, W_k, b_k, W_e2, b_e2, w_attn);
    mega1_kernel<<<257, 256, GEMM_SMEM>>>(desc, nv);
    mega3_kernel<<<168, 256, EDGE_SMEM>>>(ln_g, ln_b, b_attn, scores);
    softmax_ctx_kernel<<<dim3(Bn*Hn, 8), 256>>>(scores);
    gemm_out_kernel<<<68, 256, GEMM_SMEM>>>(W_o, b_o, outp);
}

// round 12
// speedup vs baseline: 1.0400x; 1.0400x over previous
#include <cuda_runtime.h>
#include <math.h>

#define Bn 8
#define Sn 128
#define Nn 129
#define Dn 256
#define Hn 8

#define NEG_BIG 1.0e9f
#define NEG_INF (-3.402823466e38f)

// ------------------------- scratch (device globals; no allocs) ----------------
__device__ float g_wa [Dn*Dn];
__device__ float g_wb [Dn*Dn];
__device__ float g_ba [Dn];
__device__ float g_bb [Dn];
__device__ float g_a  [Bn*Sn*Dn];
__device__ float g_bm [Bn*Sn*Dn];
__device__ float g_v  [Bn*Nn*Dn];
__device__ float g_ctx[Bn*Nn*Dn];
__device__ float g_qs [Bn*Nn*Hn];
__device__ float g_ks [Bn*Nn*Hn];
__device__ float g_wqe[Dn*Hn];
__device__ float g_wke[Dn*Hn];
__device__ float g_u  [Dn*Hn];
__device__ float g_qb [Hn];
__device__ float g_kb [Hn];
__device__ float g_ub [Hn];
__device__ unsigned char g_na[Bn*Nn*Nn];

// ------------------------- 8-way head reduce (split butterfly) ---------------
__device__ __forceinline__ float reduce8(const float acc[8], int lane) {
    const unsigned FULL = 0xffffffffu;
    bool hi16 = (lane & 16) != 0;
    float s0 = hi16 ? acc[0] : acc[4];
    float s1 = hi16 ? acc[1] : acc[5];
    float s2 = hi16 ? acc[2] : acc[6];
    float s3 = hi16 ? acc[3] : acc[7];
    float r0 = __shfl_xor_sync(FULL, s0, 16);
    float r1 = __shfl_xor_sync(FULL, s1, 16);
    float r2 = __shfl_xor_sync(FULL, s2, 16);
    float r3 = __shfl_xor_sync(FULL, s3, 16);
    float v0 = (hi16 ? acc[4] : acc[0]) + r0;
    float v1 = (hi16 ? acc[5] : acc[1]) + r1;
    float v2 = (hi16 ? acc[6] : acc[2]) + r2;
    float v3 = (hi16 ? acc[7] : acc[3]) + r3;
    bool hi8 = (lane & 8) != 0;
    float t0 = hi8 ? v0 : v2;
    float t1 = hi8 ? v1 : v3;
    float q0 = __shfl_xor_sync(FULL, t0, 8);
    float q1 = __shfl_xor_sync(FULL, t1, 8);
    float w0 = (hi8 ? v2 : v0) + q0;
    float w1 = (hi8 ? v3 : v1) + q1;
    bool hi4 = (lane & 4) != 0;
    float u0 = hi4 ? w0 : w1;
    float p0 = __shfl_xor_sync(FULL, u0, 4);
    float x = (hi4 ? w1 : w0) + p0;
    x += __shfl_xor_sync(FULL, x, 2);
    x += __shfl_xor_sync(FULL, x, 1);
    return __shfl_sync(FULL, x, (lane & 7) << 2);
}

// ------------------------- fp32 GEMM tile (device fn, dyn smem) --------------
// C[bm:bm+64, bn:bn+64] = A(MxK=256) @ W(256x256) + bias
#define TM 64
#define TN 64
#define TK 16
#define NIT (Dn/TK)
#define GEMM_SMEM ((2*TK*(TM+4) + 2*TK*TN)*4)

__device__ __forceinline__ void gemm_tile(const float* __restrict__ A, const float* __restrict__ W,
                                          const float* __restrict__ bias, float* __restrict__ C,
                                          int M, int bm, int bn, char* raw) {
    float (*As)[TM+4] = (float (*)[TM+4])raw;                         // [2*TK][TM+4]
    float (*Ws)[TN]   = (float (*)[TN])(raw + 2*TK*(TM+4)*4);         // [2*TK][TN]
    int tid = threadIdx.x;

    int arow = tid >> 2;            // 0..63
    int ak   = (tid & 3) << 2;      // 0,4,8,12
    int wrow = tid >> 4;            // 0..15
    int wc   = (tid & 15) << 2;     // 0..60

    const float* Aptr = A + (size_t)(bm + arow) * Dn + ak;
    const float* Wptr = W + (size_t)wrow * Dn + bn + wc;
    bool arow_ok = (bm + arow) < M;

    float4 av = arow_ok ? *(const float4*)Aptr : make_float4(0.f,0.f,0.f,0.f);
    float4 wv = *(const float4*)Wptr;
    As[ak+0][arow]=av.x; As[ak+1][arow]=av.y;
    As[ak+2][arow]=av.z; As[ak+3][arow]=av.w;
    *(float4*)&Ws[wrow][wc] = wv;
    __syncthreads();

    int tx = tid & 15, ty = tid >> 4;
    float acc[4][4];
    #pragma unroll
    for (int r = 0; r < 4; r++)
        #pragma unroll
        for (int c = 0; c < 4; c++) acc[r][c] = 0.f;

    #pragma unroll 2
    for (int it = 0; it < NIT; it++) {
        int cb = (it & 1) * TK;
        if (it + 1 < NIT) {
            av = arow_ok ? *(const float4*)(Aptr + (it+1)*TK) : make_float4(0.f,0.f,0.f,0.f);
            wv = *(const float4*)(Wptr + (size_t)(it+1)*TK*Dn);
        }
        #pragma unroll
        for (int k = 0; k < TK; k++) {
            float4 ra = *(const float4*)&As[cb + k][ty << 2];
            float4 rb = *(const float4*)&Ws[cb + k][tx << 2];
            acc[0][0]=fmaf(ra.x,rb.x,acc[0][0]); acc[0][1]=fmaf(ra.x,rb.y,acc[0][1]);
            acc[0][2]=fmaf(ra.x,rb.z,acc[0][2]); acc[0][3]=fmaf(ra.x,rb.w,acc[0][3]);
            acc[1][0]=fmaf(ra.y,rb.x,acc[1][0]); acc[1][1]=fmaf(ra.y,rb.y,acc[1][1]);
            acc[1][2]=fmaf(ra.y,rb.z,acc[1][2]); acc[1][3]=fmaf(ra.y,rb.w,acc[1][3]);
            acc[2][0]=fmaf(ra.z,rb.x,acc[2][0]); acc[2][1]=fmaf(ra.z,rb.y,acc[2][1]);
            acc[2][2]=fmaf(ra.z,rb.z,acc[2][2]); acc[2][3]=fmaf(ra.z,rb.w,acc[2][3]);
            acc[3][0]=fmaf(ra.w,rb.x,acc[3][0]); acc[3][1]=fmaf(ra.w,rb.y,acc[3][1]);
            acc[3][2]=fmaf(ra.w,rb.z,acc[3][2]); acc[3][3]=fmaf(ra.w,rb.w,acc[3][3]);
        }
        if (it + 1 < NIT) {
            int nb = (cb ^ TK);
            As[nb + ak+0][arow]=av.x; As[nb + ak+1][arow]=av.y;
            As[nb + ak+2][arow]=av.z; As[nb + ak+3][arow]=av.w;
            *(float4*)&Ws[nb + wrow][wc] = wv;
        }
        __syncthreads();
    }

    float4 bvec = make_float4(0.f,0.f,0.f,0.f);
    if (bias) bvec = *(const float4*)&bias[bn + (tx << 2)];
    #pragma unroll
    for (int r = 0; r < 4; r++) {
        int row = bm + (ty << 2) + r;
        if (row < M) {
            float4 o;
            o.x = acc[r][0] + bvec.x; o.y = acc[r][1] + bvec.y;
            o.z = acc[r][2] + bvec.z; o.w = acc[r][3] + bvec.w;
            *(float4*)&C[(size_t)row * Dn + bn + (tx << 2)] = o;
        }
    }
}

// ------------------------- weight fold: warp per row -------------------------
__device__ __forceinline__ void fold_row(const float* __restrict__ src,
                                         const float* __restrict__ wv,
                                         float* __restrict__ dst, int lane) {
    float w = wv[lane];
    float acc[8];
    #pragma unroll
    for (int h = 0; h < 8; h++) acc[h] = src[h*32 + lane] * w;
    float r = reduce8(acc, lane);
    if (lane < 8) dst[lane] = r;
}

__device__ void fold_block(int fb, const float* __restrict__ Wq, const float* __restrict__ bq,
                           const float* __restrict__ Wk, const float* __restrict__ bk,
                           const float* __restrict__ We2, const float* __restrict__ be2,
                           const float* __restrict__ wattn) {
    int warp = threadIdx.x >> 5, lane = threadIdx.x & 31;
    int wg = fb * 8 + warp;               // 0..95
    const float* wq = wattn;
    const float* wk = wattn + 32;
    const float* we = wattn + 64;
    #pragma unroll
    for (int rr = 0; rr < 8; rr++) {
        int row = wg + 96*rr;             // 0..767
        int mat = row >> 8, d = row & 255;
        if (mat == 0)      fold_row(Wq  + (size_t)d*Dn, wq, g_wqe + d*Hn, lane);
        else if (mat == 1) fold_row(Wk  + (size_t)d*Dn, wk, g_wke + d*Hn, lane);
        else               fold_row(We2 + (size_t)d*Dn, we, g_u   + d*Hn, lane);
    }
    if (wg == 0)      fold_row(bq,  wq, g_qb, lane);
    else if (wg == 1) fold_row(bk,  wk, g_kb, lane);
    else if (wg == 2) fold_row(be2, we, g_ub, lane);
}

// ------------------------- bias fold: ba = b_gt@W_e1a + b_e1, bb = b_gt@W_e1b
__device__ void bias_fold(const float* __restrict__ b_gt, const float* __restrict__ W_e1,
                          const float* __restrict__ b_e1) {
    int j = threadIdx.x;                  // 256 threads, column j
    float sa = 0.f, sb = 0.f;
    for (int k = 0; k < Dn; k++) {
        float g = b_gt[k];
        sa = fmaf(g, W_e1[(size_t)k*Dn + j], sa);
        sb = fmaf(g, W_e1[(size_t)(Dn + k)*Dn + j], sb);
    }
    g_ba[j] = sa + b_e1[j];
    g_bb[j] = sb;
}

// ------------------------- adjacency sign mask tile --------------------------
#define NA_PAD 264
#define NA_SMEM (2*32*NA_PAD*4)
__device__ void na_tile(const float* __restrict__ nv, int b, int it, int jt, char* raw) {
    float* sI = (float*)raw;
    float* sJ = sI + 32*NA_PAD;
    int tid = threadIdx.x;
    for (int idx = tid; idx < 32*64; idx += 256) {
        int row = idx >> 6;
        int c4  = (idx & 63) * 4;
        *(float4*)&sI[row*NA_PAD + c4] = *(const float4*)&nv[(size_t)(b*Nn + 1 + it*32 + row)*Dn + c4];
        *(float4*)&sJ[row*NA_PAD + c4] = *(const float4*)&nv[(size_t)(b*Nn + 1 + jt*32 + row)*Dn + c4];
    }
    __syncthreads();
    int tx = tid & 15, ty = tid >> 4;
    int i0 = ty*2, j0 = tx*2;
    const float* pi0 = sI + i0*NA_PAD;
    const float* pi1 = pi0 + NA_PAD;
    const float* pj0 = sJ + j0*NA_PAD;
    const float* pj1 = pj0 + NA_PAD;
    float a00 = 0.f, a01 = 0.f, a10 = 0.f, a11 = 0.f;
    for (int d = 0; d < Dn; d += 4) {
        float4 x0 = *(const float4*)(pi0 + d);
        float4 x1 = *(const float4*)(pi1 + d);
        float4 y0 = *(const float4*)(pj0 + d);
        float4 y1 = *(const float4*)(pj1 + d);
        a00 += x0.x*y0.x + x0.y*y0.y + x0.z*y0.z + x0.w*y0.w;
        a01 += x0.x*y1.x + x0.y*y1.y + x0.z*y1.z + x0.w*y1.w;
        a10 += x1.x*y0.x + x1.y*y0.y + x1.z*y0.z + x1.w*y0.w;
        a11 += x1.x*y1.x + x1.y*y1.y + x1.z*y1.z + x1.w*y1.w;
    }
    int gi = it*32 + i0, gj = jt*32 + j0;
    g_na[(size_t)(b*Nn + 1+gi  )*Nn + 1+gj  ] = (a00 > 0.f) && (gi   != gj  );
    g_na[(size_t)(b*Nn + 1+gi  )*Nn + 1+gj+1] = (a01 > 0.f) && (gi   != gj+1);
    g_na[(size_t)(b*Nn + 1+gi+1)*Nn + 1+gj  ] = (a10 > 0.f) && (gi+1 != gj  );
    g_na[(size_t)(b*Nn + 1+gi+1)*Nn + 1+gj+1] = (a11 > 0.f) && (gi+1 != gj+1);
}

// ------------------------- qs/ks tile: warp per row --------------------------
__device__ void qsks_tile(const float* __restrict__ nv, int qb, char* raw) {
    float* swq = (float*)raw;
    float* swk = swq + Dn*Hn;
    int tid = threadIdx.x;
    for (int i = tid; i < Dn*Hn; i += 256) { swq[i] = g_wqe[i]; swk[i] = g_wke[i]; }
    __syncthreads();
    int warp = tid >> 5, lane = tid & 31;
    int r = qb * 8 + warp;
    if (r >= Bn*Nn) return;
    const float* row = nv + (size_t)r * Dn;
    int dlo = lane*4, dhi = 128 + lane*4;
    float4 x0 = *(const float4*)(row + dlo);
    float4 x1 = *(const float4*)(row + dhi);
    float xv[8] = {x0.x,x0.y,x0.z,x0.w,x1.x,x1.y,x1.z,x1.w};
    float aq[8] = {0,0,0,0,0,0,0,0};
    float ak[8] = {0,0,0,0,0,0,0,0};
    #pragma unroll
    for (int rr = 0; rr < 8; rr++) {
        int d = (rr < 4) ? (dlo + rr) : (dhi + rr - 4);
        float4 wqa = *(const float4*)&swq[d*Hn];
        float4 wqb = *(const float4*)&swq[d*Hn + 4];
        float4 wka = *(const float4*)&swk[d*Hn];
        float4 wkb = *(const float4*)&swk[d*Hn + 4];
        float x = xv[rr];
        aq[0]=fmaf(x,wqa.x,aq[0]); aq[1]=fmaf(x,wqa.y,aq[1]);
        aq[2]=fmaf(x,wqa.z,aq[2]); aq[3]=fmaf(x,wqa.w,aq[3]);
        aq[4]=fmaf(x,wqb.x,aq[4]); aq[5]=fmaf(x,wqb.y,aq[5]);
        aq[6]=fmaf(x,wqb.z,aq[6]); aq[7]=fmaf(x,wqb.w,aq[7]);
        ak[0]=fmaf(x,wka.x,ak[0]); ak[1]=fmaf(x,wka.y,ak[1]);
        ak[2]=fmaf(x,wka.z,ak[2]); ak[3]=fmaf(x,wka.w,ak[3]);
        ak[4]=fmaf(x,wkb.x,ak[4]); ak[5]=fmaf(x,wkb.y,ak[5]);
        ak[6]=fmaf(x,wkb.z,ak[6]); ak[7]=fmaf(x,wkb.w,ak[7]);
    }
    float rq = reduce8(aq, lane);
    float rk = reduce8(ak, lane);
    if (lane < Hn) {
        g_qs[r*Hn + lane] = rq + g_qb[lane];
        g_ks[r*Hn + lane] = rk + g_kb[lane];
    }
}

// ------------------------- per-edge LN + relu + 8-head dot -------------------
__device__ __forceinline__ float edge_ln_dot8(const float x[8], const float gg[8],
                                              const float bbv[8], const float ur[8][8],
                                              int lane) {
    float s = 0.f, ss = 0.f;
    #pragma unroll
    for (int r = 0; r < 8; r++) { s += x[r]; ss = fmaf(x[r], x[r], ss); }
    #pragma unroll
    for (int off = 16; off; off >>= 1) {
        s  += __shfl_xor_sync(0xffffffffu, s,  off);
        ss += __shfl_xor_sync(0xffffffffu, ss, off);
    }
    float mu  = s  * (1.f/256.f);
    float var = ss * (1.f/256.f) - mu*mu;
    float rs  = 1.f / sqrtf(var + 1e-5f);
    float nm  = -mu * rs;
    float acc[8] = {0.f,0.f,0.f,0.f,0.f,0.f,0.f,0.f};
    #pragma unroll
    for (int r = 0; r < 8; r++) {
        float t = fmaf(x[r], rs, nm);
        t = fmaf(t, gg[r], bbv[r]);
        t = fmaxf(t, 0.f);
        #pragma unroll
        for (int h = 0; h < Hn; h++) acc[h] = fmaf(t, ur[r][h], acc[h]);
    }
    return reduce8(acc, lane);
}

__device__ __forceinline__ void edge_preload(int lane, const float* __restrict__ ln_g,
                                             const float* __restrict__ ln_b,
                                             float gg[8], float bbv[8], float ur[8][8]) {
    int dlo = lane*4, dhi = 128 + lane*4;
    #pragma unroll
    for (int r = 0; r < 4; r++) {
        gg [r]   = ln_g[dlo+r]; bbv[r]   = ln_b[dlo+r];
        gg [4+r] = ln_g[dhi+r]; bbv[4+r] = ln_b[dhi+r];
        #pragma unroll
        for (int h = 0; h < Hn; h++) {
            ur[r][h]   = g_u[(dlo+r)*Hn + h];
            ur[4+r][h] = g_u[(dhi+r)*Hn + h];
        }
    }
}

// ------------------------- edges for row i==0 --------------------------------
__device__ void edge_row0(int b, const float* __restrict__ ln_g, const float* __restrict__ ln_b,
                          float battn, float* __restrict__ scores) {
    int tid = threadIdx.x, warp = tid >> 5, lane = tid & 31;
    float gg[8], bbv[8], ur[8][8];
    edge_preload(lane, ln_g, ln_b, gg, bbv, ur);
    float ub = (lane < Hn) ? g_ub[lane] : 0.f;
    int dlo = lane*4, dhi = 128 + lane*4;

    for (int j = warp; j <= 128; j += 8) {
        if (j == 0) {
            if (lane < Hn) {
                float sc = g_qs[(b*Nn+0)*Hn + lane] + g_ks[(b*Nn+0)*Hn + lane] + battn - NEG_BIG;
                scores[((size_t)(b*Hn + lane)*Nn + 0)*Nn + 0] = sc;
            }
            continue;
        }
        int s = j - 1;
        const float* ar = g_a  + (size_t)(b*Sn + s)*Dn;
        const float* br = g_bm + (size_t)(b*Sn + s)*Dn;
        float4 a0 = *(const float4*)(ar + dlo), b0 = *(const float4*)(br + dlo);
        float4 a1 = *(const float4*)(ar + dhi), b1 = *(const float4*)(br + dhi);
        float x[8];
        x[0]=a0.x+b0.x; x[1]=a0.y+b0.y; x[2]=a0.z+b0.z; x[3]=a0.w+b0.w;
        x[4]=a1.x+b1.x; x[5]=a1.y+b1.y; x[6]=a1.z+b1.z; x[7]=a1.w+b1.w;
        float edot = edge_ln_dot8(x, gg, bbv, ur, lane);
        if (lane < Hn) {
            float sc = g_qs[(b*Nn+0)*Hn + lane] + g_ks[(b*Nn+j)*Hn + lane] + battn
                     + edot + ub;
            scores[((size_t)(b*Hn + lane)*Nn + 0)*Nn + j] = sc;
        }
    }
}

// ------------------------- main edge tile (i in 1..128) ----------------------
// smem: bT[32*256] qsT[32*8] ksT[32*8] scT[8*1025] naT[1024]
#define SCT_PITCH 1025
#define EDGE_SMEM ((32*256 + 32*8 + 32*8 + 8*SCT_PITCH)*4 + 1024)
__device__ void edge_main(int b, int it, int jt,
                          const float* __restrict__ ln_g, const float* __restrict__ ln_b,
                          float battn, float* __restrict__ scores, char* raw) {
    float* bT  = (float*)raw;
    float* qsT = bT + 32*256;
    float* ksT = qsT + 32*8;
    float* scT = ksT + 32*8;
    unsigned char* naT = (unsigned char*)(scT + 8*SCT_PITCH);

    int tid = threadIdx.x, warp = tid >> 5, lane = tid & 31;

    for (int idx = tid; idx < 32*64; idx += 256) {
        int row = idx >> 6;
        int c4  = (idx & 63) * 4;
        int j = jt*32 + row;
        float4 bv = make_float4(0.f,0.f,0.f,0.f);
        if (j >= 1 && j <= 128)
            bv = *(const float4*)&g_bm[(size_t)(b*Sn + j - 1)*Dn + c4];
        *(float4*)&bT[row*256 + c4] = bv;
    }
    {
        int r = tid >> 3, h = tid & 7;
        int i = 1 + it*32 + r;
        qsT[tid] = g_qs[(size_t)(b*Nn + i)*Hn + h];
        int j = jt*32 + r;
        ksT[tid] = (j <= 128) ? g_ks[(size_t)(b*Nn + j)*Hn + h] : 0.f;
    }
    for (int idx = tid; idx < 1024; idx += 256) {
        int ei = idx >> 5, ej = idx & 31;
        int j = jt*32 + ej;
        int i = 1 + it*32 + ei;
        naT[idx] = (j >= 1 && j <= 128) ? g_na[(size_t)(b*Nn + i)*Nn + j] : 0;
    }

    float gg[8], bbv[8], ur[8][8];
    edge_preload(lane, ln_g, ln_b, gg, bbv, ur);
    float ub = (lane < Hn) ? g_ub[lane] : 0.f;
    __syncthreads();

    #pragma unroll
    for (int eib = 0; eib < 4; eib++) {
        int ei = warp + eib*8;                   // 0..31
        const float* ar = g_a + (size_t)(b*Sn + it*32 + ei)*Dn;
        float4 a0 = *(const float4*)(ar + lane*4);
        float4 a1 = *(const float4*)(ar + 128 + lane*4);
        for (int ej = 0; ej < 32; ej++) {
            int j = jt*32 + ej;
            if (j > 128) continue;
            int slot = ei*32 + ej;
            unsigned char mk = naT[slot];
            float edot = 0.f;
            if (mk) {
                const float* brow = bT + ej*256;
                float4 b0 = *(const float4*)(brow + lane*4);
                float4 b1 = *(const float4*)(brow + 128 + lane*4);
                float x[8];
                x[0]=a0.x+b0.x; x[1]=a0.y+b0.y; x[2]=a0.z+b0.z; x[3]=a0.w+b0.w;
                x[4]=a1.x+b1.x; x[5]=a1.y+b1.y; x[6]=a1.z+b1.z; x[7]=a1.w+b1.w;
                edot = edge_ln_dot8(x, gg, bbv, ur, lane);
            }
            if (lane < Hn) {
                float sc = qsT[ei*8 + lane] + ksT[ej*8 + lane] + battn;
                sc = mk ? (sc + edot + ub) : (sc - NEG_BIG);
                scT[lane*SCT_PITCH + slot] = sc;
            }
        }
    }
    __syncthreads();
    for (int idx = tid; idx < 8192; idx += 256) {
        int h    = idx >> 10;
        int slot = idx & 1023;
        int ei   = slot >> 5;
        int ej   = slot & 31;
        int j = jt*32 + ej;
        if (j <= 128) {
            int i = 1 + it*32 + ei;
            scores[((size_t)(b*Hn + h)*Nn + i)*Nn + j] = scT[h*SCT_PITCH + slot];
        }
    }
}

// ========================= phase mega-kernels ================================

// P0: Wa GEMM (16) | Wb GEMM (16) | v GEMM (68) | na (128) | fold (12) | bias (1) = 241
__global__ void __launch_bounds__(256)
mega0_kernel(const float* __restrict__ W_gt, const float* __restrict__ W_e1,
             const float* __restrict__ b_gt, const float* __restrict__ b_e1,
             const float* __restrict__ nv,   const float* __restrict__ W_v, const float* __restrict__ b_v,
             const float* __restrict__ W_q,  const float* __restrict__ b_q,
             const float* __restrict__ W_k,  const float* __restrict__ b_k,
             const float* __restrict__ We2,  const float* __restrict__ be2,
             const float* __restrict__ wattn) {
    extern __shared__ char raw[];
    int id = blockIdx.x;
    if (id < 16)  { gemm_tile(W_gt, W_e1, nullptr, g_wa, Dn, (id>>2)*TM, (id&3)*TN, raw); return; }
    id -= 16;
    if (id < 16)  { gemm_tile(W_gt, W_e1 + Dn*Dn, nullptr, g_wb, Dn, (id>>2)*TM, (id&3)*TN, raw); return; }
    id -= 16;
    if (id < 68)  { gemm_tile(nv, W_v, b_v, g_v, Bn*Nn, (id>>2)*TM, (id&3)*TN, raw); return; }
    id -= 68;
    if (id < 128) { na_tile(nv, id >> 4, (id >> 2) & 3, id & 3, raw); return; }
    id -= 128;
    if (id < 12)  { fold_block(id, W_q, b_q, W_k, b_k, We2, be2, wattn); return; }
    bias_fold(b_gt, W_e1, b_e1);
}

// P1: a GEMM (64) | b GEMM (64) | qsks (129) = 257
__global__ void __launch_bounds__(256)
mega1_kernel(const float* __restrict__ desc, const float* __restrict__ nv) {
    extern __shared__ char raw[];
    int id = blockIdx.x;
    if (id < 64)  { gemm_tile(desc, g_wa, g_ba, g_a, Bn*Sn, (id>>2)*TM, (id&3)*TN, raw); return; }
    id -= 64;
    if (id < 64)  { gemm_tile(desc, g_wb, g_bb, g_bm, Bn*Sn, (id>>2)*TM, (id&3)*TN, raw); return; }
    id -= 64;
    qsks_tile(nv, id, raw);
}

// P2: edge_row0 (8) | edge_main (160)  = 168 blocks
__global__ void __launch_bounds__(256)
mega3_kernel(const float* __restrict__ ln_g, const float* __restrict__ ln_b,
             const float* __restrict__ p_battn, float* __restrict__ scores) {
    extern __shared__ char raw[];
    float battn = *p_battn;
    int id = blockIdx.x;
    if (id < 8) { edge_row0(id, ln_g, ln_b, battn, scores); return; }
    id -= 8;
    int b = id / 20, rem = id % 20;
    edge_main(b, rem / 5, rem % 5, ln_g, ln_b, battn, scores, raw);
}

// P3: fused softmax + ctx (grid 64 x 4), single-row with next-row prefetch
__device__ __forceinline__ void softmax_row_load(const float* __restrict__ p, int lane,
                                                 float v[5], float& m) {
    m = NEG_INF;
    #pragma unroll
    for (int k = 0; k < 5; k++) {
        int j = k*32 + lane;
        v[k] = (j < Nn) ? p[j] : NEG_INF;
        m = fmaxf(m, v[k]);
    }
}

__global__ void __launch_bounds__(256) softmax_ctx_kernel(float* __restrict__ scores) {
    __shared__ float vT[Nn][33];
    int bh = blockIdx.x;
    int b = bh >> 3, h = bh & 7;
    int tid = threadIdx.x, warp = tid >> 5, lane = tid & 31;
    for (int idx = tid; idx < Nn*32; idx += 256) {
        int j = idx >> 5, c = idx & 31;
        vT[j][c] = g_v[(size_t)(b*Nn + j)*Dn + h*32 + c];
    }
    __syncthreads();
    const unsigned FULL = 0xffffffffu;
    const float* base = scores + (size_t)(b*Hn + h)*Nn*Nn;

    int start = blockIdx.y*8 + warp;     // 0..31
    float v[5], m;
    softmax_row_load(base + (size_t)start*Nn, lane, v, m);

    for (int i = start; i < Nn; i += 32) {
        float* prow = scores + ((size_t)(b*Hn + h)*Nn + i)*Nn;
        #pragma unroll
        for (int off = 16; off; off >>= 1) m = fmaxf(m, __shfl_xor_sync(FULL, m, off));
        float sum = 0.f;
        #pragma unroll
        for (int k = 0; k < 5; k++) {
            int j = k*32 + lane;
            if (j < Nn) { v[k] = expf(v[k] - m); sum += v[k]; }
            else        { v[k] = 0.f; }
        }
        #pragma unroll
        for (int off = 16; off; off >>= 1) sum += __shfl_xor_sync(FULL, sum, off);
        float inv = 1.f / sum;
        #pragma unroll
        for (int k = 0; k < 5; k++) {
            int j = k*32 + lane;
            v[k] *= inv;
            if (j < Nn) prow[j] = v[k];
        }
        // prefetch next row while the ctx FMA loop below runs
        float vn[5] = {0.f,0.f,0.f,0.f,0.f};
        float mn = NEG_INF;
        int inext = i + 32;
        if (inext < Nn)
            softmax_row_load(base + (size_t)inext*Nn, lane, vn, mn);
        // attn @ V with 4 independent accumulator chains
        float acc0 = 0.f, acc1 = 0.f, acc2 = 0.f, acc3 = 0.f;
        #pragma unroll
        for (int jj = 0; jj < 128; jj += 4) {
            float r  = v[jj >> 5];           // same source reg for jj..jj+3
            float a0 = __shfl_sync(FULL, r, (jj+0) & 31);
            float a1 = __shfl_sync(FULL, r, (jj+1) & 31);
            float a2 = __shfl_sync(FULL, r, (jj+2) & 31);
            float a3 = __shfl_sync(FULL, r, (jj+3) & 31);
            acc0 = fmaf(a0, vT[jj+0][lane], acc0);
            acc1 = fmaf(a1, vT[jj+1][lane], acc1);
            acc2 = fmaf(a2, vT[jj+2][lane], acc2);
            acc3 = fmaf(a3, vT[jj+3][lane], acc3);
        }
        float aLast = __shfl_sync(FULL, v[4], 0);
        acc0 = fmaf(aLast, vT[128][lane], acc0);
        g_ctx[(size_t)(b*Nn + i)*Dn + h*32 + lane] = (acc0 + acc1) + (acc2 + acc3);
        #pragma unroll
        for (int k = 0; k < 5; k++) v[k] = vn[k];
        m = mn;
    }
}

// P4: ctx -> out GEMM (68 blocks)
__global__ void __launch_bounds__(256)
gemm_out_kernel(const float* __restrict__ W_o, const float* __restrict__ b_o,
                float* __restrict__ outp) {
    extern __shared__ char raw[];
    int id = blockIdx.x;
    gemm_tile(g_ctx, W_o, b_o, outp, Bn*Nn, (id>>2)*TM, (id&3)*TN, raw);
}

// ------------------------- launch --------------------------------------------
extern "C" void kernel_launch(void* const* d_in, const int* in_sizes, int n_in,
                              void* d_out, int out_size) {
    const float* desc   = (const float*)d_in[0];
    const float* nv     = (const float*)d_in[1];
    const float* W_gt   = (const float*)d_in[2];
    const float* b_gt   = (const float*)d_in[3];
    // d_in[4] = topo_bias: irrelevant to forward value (sigmoid>0 always)
    const float* W_q    = (const float*)d_in[5];
    const float* b_q    = (const float*)d_in[6];
    const float* W_k    = (const float*)d_in[7];
    const float* b_k    = (const float*)d_in[8];
    const float* W_v    = (const float*)d_in[9];
    const float* b_v    = (const float*)d_in[10];
    const float* W_e1   = (const float*)d_in[11];
    const float* b_e1   = (const float*)d_in[12];
    const float* ln_g   = (const float*)d_in[13];
    const float* ln_b   = (const float*)d_in[14];
    const float* W_e2   = (const float*)d_in[15];
    const float* b_e2   = (const float*)d_in[16];
    const float* w_attn = (const float*)d_in[17];
    const float* b_attn = (const float*)d_in[18];
    const float* W_o    = (const float*)d_in[19];
    const float* b_o    = (const float*)d_in[20];

    float* outp   = (float*)d_out;
    float* scores = outp + Bn*Nn*Dn;     // attn region of output, used in place

    cudaFuncSetAttribute(mega0_kernel, cudaFuncAttributeMaxDynamicSharedMemorySize, NA_SMEM);
    cudaFuncSetAttribute(mega3_kernel, cudaFuncAttributeMaxDynamicSharedMemorySize, EDGE_SMEM);

    mega0_kernel<<<241, 256, NA_SMEM>>>(W_gt, W_e1, b_gt, b_e1, nv, W_v, b_v,
                                        W_q, b_q, W_k, b_k, W_e2, b_e2, w_attn);
    mega1_kernel<<<257, 256, GEMM_SMEM>>>(desc, nv);
    mega3_kernel<<<168, 256, EDGE_SMEM>>>(ln_g, ln_b, b_attn, scores);
    softmax_ctx_kernel<<<dim3(Bn*Hn, 4), 256>>>(scores);
    gemm_out_kernel<<<68, 256, GEMM_SMEM>>>(W_o, b_o, outp);
}

// round 13
// speedup vs baseline: 1.0807x; 1.0391x over previous
#include <cuda_runtime.h>
#include <math.h>

#define Bn 8
#define Sn 128
#define Nn 129
#define Dn 256
#define Hn 8

#define NEG_BIG 1.0e9f
#define NEG_INF (-3.402823466e38f)

// ------------------------- scratch (device globals; no allocs) ----------------
__device__ float g_wa [Dn*Dn];
__device__ float g_wb [Dn*Dn];
__device__ float g_ba [Dn];
__device__ float g_bb [Dn];
__device__ float g_a  [Bn*Sn*Dn];
__device__ float g_bm [Bn*Sn*Dn];
__device__ float g_v  [Bn*Nn*Dn];
__device__ float g_ctx[Bn*Nn*Dn];
__device__ float g_qs [Bn*Nn*Hn];
__device__ float g_ks [Bn*Nn*Hn];
__device__ float g_wqe[Dn*Hn];
__device__ float g_wke[Dn*Hn];
__device__ float g_u  [Dn*Hn];
__device__ float g_qb [Hn];
__device__ float g_kb [Hn];
__device__ float g_ub [Hn];
__device__ unsigned char g_na[Bn*Nn*Nn];

// ------------------------- 8-way head reduce (split butterfly) ---------------
__device__ __forceinline__ float reduce8(const float acc[8], int lane) {
    const unsigned FULL = 0xffffffffu;
    bool hi16 = (lane & 16) != 0;
    float s0 = hi16 ? acc[0] : acc[4];
    float s1 = hi16 ? acc[1] : acc[5];
    float s2 = hi16 ? acc[2] : acc[6];
    float s3 = hi16 ? acc[3] : acc[7];
    float r0 = __shfl_xor_sync(FULL, s0, 16);
    float r1 = __shfl_xor_sync(FULL, s1, 16);
    float r2 = __shfl_xor_sync(FULL, s2, 16);
    float r3 = __shfl_xor_sync(FULL, s3, 16);
    float v0 = (hi16 ? acc[4] : acc[0]) + r0;
    float v1 = (hi16 ? acc[5] : acc[1]) + r1;
    float v2 = (hi16 ? acc[6] : acc[2]) + r2;
    float v3 = (hi16 ? acc[7] : acc[3]) + r3;
    bool hi8 = (lane & 8) != 0;
    float t0 = hi8 ? v0 : v2;
    float t1 = hi8 ? v1 : v3;
    float q0 = __shfl_xor_sync(FULL, t0, 8);
    float q1 = __shfl_xor_sync(FULL, t1, 8);
    float w0 = (hi8 ? v2 : v0) + q0;
    float w1 = (hi8 ? v3 : v1) + q1;
    bool hi4 = (lane & 4) != 0;
    float u0 = hi4 ? w0 : w1;
    float p0 = __shfl_xor_sync(FULL, u0, 4);
    float x = (hi4 ? w1 : w0) + p0;
    x += __shfl_xor_sync(FULL, x, 2);
    x += __shfl_xor_sync(FULL, x, 1);
    return __shfl_sync(FULL, x, (lane & 7) << 2);
}

// ------------------------- fp32 GEMM tile (device fn, dyn smem) --------------
// C[bm:bm+64, bn:bn+64] = A(MxK=256) @ W(256x256) + bias
#define TM 64
#define TN 64
#define TK 16
#define NIT (Dn/TK)
#define GEMM_SMEM ((2*TK*(TM+4) + 2*TK*TN)*4)

__device__ __forceinline__ void gemm_tile(const float* __restrict__ A, const float* __restrict__ W,
                                          const float* __restrict__ bias, float* __restrict__ C,
                                          int M, int bm, int bn, char* raw) {
    float (*As)[TM+4] = (float (*)[TM+4])raw;                         // [2*TK][TM+4]
    float (*Ws)[TN]   = (float (*)[TN])(raw + 2*TK*(TM+4)*4);         // [2*TK][TN]
    int tid = threadIdx.x;

    int arow = tid >> 2;            // 0..63
    int ak   = (tid & 3) << 2;      // 0,4,8,12
    int wrow = tid >> 4;            // 0..15
    int wc   = (tid & 15) << 2;     // 0..60

    const float* Aptr = A + (size_t)(bm + arow) * Dn + ak;
    const float* Wptr = W + (size_t)wrow * Dn + bn + wc;
    bool arow_ok = (bm + arow) < M;

    float4 av = arow_ok ? *(const float4*)Aptr : make_float4(0.f,0.f,0.f,0.f);
    float4 wv = *(const float4*)Wptr;
    As[ak+0][arow]=av.x; As[ak+1][arow]=av.y;
    As[ak+2][arow]=av.z; As[ak+3][arow]=av.w;
    *(float4*)&Ws[wrow][wc] = wv;
    __syncthreads();

    int tx = tid & 15, ty = tid >> 4;
    float acc[4][4];
    #pragma unroll
    for (int r = 0; r < 4; r++)
        #pragma unroll
        for (int c = 0; c < 4; c++) acc[r][c] = 0.f;

    #pragma unroll 2
    for (int it = 0; it < NIT; it++) {
        int cb = (it & 1) * TK;
        if (it + 1 < NIT) {
            av = arow_ok ? *(const float4*)(Aptr + (it+1)*TK) : make_float4(0.f,0.f,0.f,0.f);
            wv = *(const float4*)(Wptr + (size_t)(it+1)*TK*Dn);
        }
        #pragma unroll
        for (int k = 0; k < TK; k++) {
            float4 ra = *(const float4*)&As[cb + k][ty << 2];
            float4 rb = *(const float4*)&Ws[cb + k][tx << 2];
            acc[0][0]=fmaf(ra.x,rb.x,acc[0][0]); acc[0][1]=fmaf(ra.x,rb.y,acc[0][1]);
            acc[0][2]=fmaf(ra.x,rb.z,acc[0][2]); acc[0][3]=fmaf(ra.x,rb.w,acc[0][3]);
            acc[1][0]=fmaf(ra.y,rb.x,acc[1][0]); acc[1][1]=fmaf(ra.y,rb.y,acc[1][1]);
            acc[1][2]=fmaf(ra.y,rb.z,acc[1][2]); acc[1][3]=fmaf(ra.y,rb.w,acc[1][3]);
            acc[2][0]=fmaf(ra.z,rb.x,acc[2][0]); acc[2][1]=fmaf(ra.z,rb.y,acc[2][1]);
            acc[2][2]=fmaf(ra.z,rb.z,acc[2][2]); acc[2][3]=fmaf(ra.z,rb.w,acc[2][3]);
            acc[3][0]=fmaf(ra.w,rb.x,acc[3][0]); acc[3][1]=fmaf(ra.w,rb.y,acc[3][1]);
            acc[3][2]=fmaf(ra.w,rb.z,acc[3][2]); acc[3][3]=fmaf(ra.w,rb.w,acc[3][3]);
        }
        if (it + 1 < NIT) {
            int nb = (cb ^ TK);
            As[nb + ak+0][arow]=av.x; As[nb + ak+1][arow]=av.y;
            As[nb + ak+2][arow]=av.z; As[nb + ak+3][arow]=av.w;
            *(float4*)&Ws[nb + wrow][wc] = wv;
        }
        __syncthreads();
    }

    float4 bvec = make_float4(0.f,0.f,0.f,0.f);
    if (bias) bvec = *(const float4*)&bias[bn + (tx << 2)];
    #pragma unroll
    for (int r = 0; r < 4; r++) {
        int row = bm + (ty << 2) + r;
        if (row < M) {
            float4 o;
            o.x = acc[r][0] + bvec.x; o.y = acc[r][1] + bvec.y;
            o.z = acc[r][2] + bvec.z; o.w = acc[r][3] + bvec.w;
            *(float4*)&C[(size_t)row * Dn + bn + (tx << 2)] = o;
        }
    }
}

// ------------------------- weight fold: warp per row -------------------------
__device__ __forceinline__ void fold_row(const float* __restrict__ src,
                                         const float* __restrict__ wv,
                                         float* __restrict__ dst, int lane) {
    float w = wv[lane];
    float acc[8];
    #pragma unroll
    for (int h = 0; h < 8; h++) acc[h] = src[h*32 + lane] * w;
    float r = reduce8(acc, lane);
    if (lane < 8) dst[lane] = r;
}

__device__ void fold_block(int fb, const float* __restrict__ Wq, const float* __restrict__ bq,
                           const float* __restrict__ Wk, const float* __restrict__ bk,
                           const float* __restrict__ We2, const float* __restrict__ be2,
                           const float* __restrict__ wattn) {
    int warp = threadIdx.x >> 5, lane = threadIdx.x & 31;
    int wg = fb * 8 + warp;               // 0..95
    const float* wq = wattn;
    const float* wk = wattn + 32;
    const float* we = wattn + 64;
    #pragma unroll
    for (int rr = 0; rr < 8; rr++) {
        int row = wg + 96*rr;             // 0..767
        int mat = row >> 8, d = row & 255;
        if (mat == 0)      fold_row(Wq  + (size_t)d*Dn, wq, g_wqe + d*Hn, lane);
        else if (mat == 1) fold_row(Wk  + (size_t)d*Dn, wk, g_wke + d*Hn, lane);
        else               fold_row(We2 + (size_t)d*Dn, we, g_u   + d*Hn, lane);
    }
    if (wg == 0)      fold_row(bq,  wq, g_qb, lane);
    else if (wg == 1) fold_row(bk,  wk, g_kb, lane);
    else if (wg == 2) fold_row(be2, we, g_ub, lane);
}

// ------------------------- bias fold: ba = b_gt@W_e1a + b_e1, bb = b_gt@W_e1b
__device__ void bias_fold(const float* __restrict__ b_gt, const float* __restrict__ W_e1,
                          const float* __restrict__ b_e1) {
    int j = threadIdx.x;                  // 256 threads, column j
    float sa = 0.f, sb = 0.f;
    for (int k = 0; k < Dn; k++) {
        float g = b_gt[k];
        sa = fmaf(g, W_e1[(size_t)k*Dn + j], sa);
        sb = fmaf(g, W_e1[(size_t)(Dn + k)*Dn + j], sb);
    }
    g_ba[j] = sa + b_e1[j];
    g_bb[j] = sb;
}

// ------------------------- adjacency sign mask tile --------------------------
#define NA_PAD 264
#define NA_SMEM (2*32*NA_PAD*4)
__device__ void na_tile(const float* __restrict__ nv, int b, int it, int jt, char* raw) {
    float* sI = (float*)raw;
    float* sJ = sI + 32*NA_PAD;
    int tid = threadIdx.x;
    for (int idx = tid; idx < 32*64; idx += 256) {
        int row = idx >> 6;
        int c4  = (idx & 63) * 4;
        *(float4*)&sI[row*NA_PAD + c4] = *(const float4*)&nv[(size_t)(b*Nn + 1 + it*32 + row)*Dn + c4];
        *(float4*)&sJ[row*NA_PAD + c4] = *(const float4*)&nv[(size_t)(b*Nn + 1 + jt*32 + row)*Dn + c4];
    }
    __syncthreads();
    int tx = tid & 15, ty = tid >> 4;
    int i0 = ty*2, j0 = tx*2;
    const float* pi0 = sI + i0*NA_PAD;
    const float* pi1 = pi0 + NA_PAD;
    const float* pj0 = sJ + j0*NA_PAD;
    const float* pj1 = pj0 + NA_PAD;
    float a00 = 0.f, a01 = 0.f, a10 = 0.f, a11 = 0.f;
    for (int d = 0; d < Dn; d += 4) {
        float4 x0 = *(const float4*)(pi0 + d);
        float4 x1 = *(const float4*)(pi1 + d);
        float4 y0 = *(const float4*)(pj0 + d);
        float4 y1 = *(const float4*)(pj1 + d);
        a00 += x0.x*y0.x + x0.y*y0.y + x0.z*y0.z + x0.w*y0.w;
        a01 += x0.x*y1.x + x0.y*y1.y + x0.z*y1.z + x0.w*y1.w;
        a10 += x1.x*y0.x + x1.y*y0.y + x1.z*y0.z + x1.w*y0.w;
        a11 += x1.x*y1.x + x1.y*y1.y + x1.z*y1.z + x1.w*y1.w;
    }
    int gi = it*32 + i0, gj = jt*32 + j0;
    g_na[(size_t)(b*Nn + 1+gi  )*Nn + 1+gj  ] = (a00 > 0.f) && (gi   != gj  );
    g_na[(size_t)(b*Nn + 1+gi  )*Nn + 1+gj+1] = (a01 > 0.f) && (gi   != gj+1);
    g_na[(size_t)(b*Nn + 1+gi+1)*Nn + 1+gj  ] = (a10 > 0.f) && (gi+1 != gj  );
    g_na[(size_t)(b*Nn + 1+gi+1)*Nn + 1+gj+1] = (a11 > 0.f) && (gi+1 != gj+1);
}

// ------------------------- qs/ks tile: warp per row --------------------------
__device__ void qsks_tile(const float* __restrict__ nv, int qb, char* raw) {
    float* swq = (float*)raw;
    float* swk = swq + Dn*Hn;
    int tid = threadIdx.x;
    for (int i = tid; i < Dn*Hn; i += 256) { swq[i] = g_wqe[i]; swk[i] = g_wke[i]; }
    __syncthreads();
    int warp = tid >> 5, lane = tid & 31;
    int r = qb * 8 + warp;
    if (r >= Bn*Nn) return;
    const float* row = nv + (size_t)r * Dn;
    int dlo = lane*4, dhi = 128 + lane*4;
    float4 x0 = *(const float4*)(row + dlo);
    float4 x1 = *(const float4*)(row + dhi);
    float xv[8] = {x0.x,x0.y,x0.z,x0.w,x1.x,x1.y,x1.z,x1.w};
    float aq[8] = {0,0,0,0,0,0,0,0};
    float ak[8] = {0,0,0,0,0,0,0,0};
    #pragma unroll
    for (int rr = 0; rr < 8; rr++) {
        int d = (rr < 4) ? (dlo + rr) : (dhi + rr - 4);
        float4 wqa = *(const float4*)&swq[d*Hn];
        float4 wqb = *(const float4*)&swq[d*Hn + 4];
        float4 wka = *(const float4*)&swk[d*Hn];
        float4 wkb = *(const float4*)&swk[d*Hn + 4];
        float x = xv[rr];
        aq[0]=fmaf(x,wqa.x,aq[0]); aq[1]=fmaf(x,wqa.y,aq[1]);
        aq[2]=fmaf(x,wqa.z,aq[2]); aq[3]=fmaf(x,wqa.w,aq[3]);
        aq[4]=fmaf(x,wqb.x,aq[4]); aq[5]=fmaf(x,wqb.y,aq[5]);
        aq[6]=fmaf(x,wqb.z,aq[6]); aq[7]=fmaf(x,wqb.w,aq[7]);
        ak[0]=fmaf(x,wka.x,ak[0]); ak[1]=fmaf(x,wka.y,ak[1]);
        ak[2]=fmaf(x,wka.z,ak[2]); ak[3]=fmaf(x,wka.w,ak[3]);
        ak[4]=fmaf(x,wkb.x,ak[4]); ak[5]=fmaf(x,wkb.y,ak[5]);
        ak[6]=fmaf(x,wkb.z,ak[6]); ak[7]=fmaf(x,wkb.w,ak[7]);
    }
    float rq = reduce8(aq, lane);
    float rk = reduce8(ak, lane);
    if (lane < Hn) {
        g_qs[r*Hn + lane] = rq + g_qb[lane];
        g_ks[r*Hn + lane] = rk + g_kb[lane];
    }
}

// ------------------------- per-edge LN + relu + 8-head dot -------------------
__device__ __forceinline__ float edge_ln_dot8(const float x[8], const float gg[8],
                                              const float bbv[8], const float ur[8][8],
                                              int lane) {
    float s = 0.f, ss = 0.f;
    #pragma unroll
    for (int r = 0; r < 8; r++) { s += x[r]; ss = fmaf(x[r], x[r], ss); }
    #pragma unroll
    for (int off = 16; off; off >>= 1) {
        s  += __shfl_xor_sync(0xffffffffu, s,  off);
        ss += __shfl_xor_sync(0xffffffffu, ss, off);
    }
    float mu  = s  * (1.f/256.f);
    float var = ss * (1.f/256.f) - mu*mu;
    float rs  = 1.f / sqrtf(var + 1e-5f);
    float nm  = -mu * rs;
    float acc[8] = {0.f,0.f,0.f,0.f,0.f,0.f,0.f,0.f};
    #pragma unroll
    for (int r = 0; r < 8; r++) {
        float t = fmaf(x[r], rs, nm);
        t = fmaf(t, gg[r], bbv[r]);
        t = fmaxf(t, 0.f);
        #pragma unroll
        for (int h = 0; h < Hn; h++) acc[h] = fmaf(t, ur[r][h], acc[h]);
    }
    return reduce8(acc, lane);
}

__device__ __forceinline__ void edge_preload(int lane, const float* __restrict__ ln_g,
                                             const float* __restrict__ ln_b,
                                             float gg[8], float bbv[8], float ur[8][8]) {
    int dlo = lane*4, dhi = 128 + lane*4;
    #pragma unroll
    for (int r = 0; r < 4; r++) {
        gg [r]   = ln_g[dlo+r]; bbv[r]   = ln_b[dlo+r];
        gg [4+r] = ln_g[dhi+r]; bbv[4+r] = ln_b[dhi+r];
        #pragma unroll
        for (int h = 0; h < Hn; h++) {
            ur[r][h]   = g_u[(dlo+r)*Hn + h];
            ur[4+r][h] = g_u[(dhi+r)*Hn + h];
        }
    }
}

// ------------------------- edges for row i==0 --------------------------------
__device__ void edge_row0(int b, const float* __restrict__ ln_g, const float* __restrict__ ln_b,
                          float battn, float* __restrict__ scores) {
    int tid = threadIdx.x, warp = tid >> 5, lane = tid & 31;
    float gg[8], bbv[8], ur[8][8];
    edge_preload(lane, ln_g, ln_b, gg, bbv, ur);
    float ub = (lane < Hn) ? g_ub[lane] : 0.f;
    int dlo = lane*4, dhi = 128 + lane*4;

    for (int j = warp; j <= 128; j += 8) {
        if (j == 0) {
            if (lane < Hn) {
                float sc = g_qs[(b*Nn+0)*Hn + lane] + g_ks[(b*Nn+0)*Hn + lane] + battn - NEG_BIG;
                scores[((size_t)(b*Hn + lane)*Nn + 0)*Nn + 0] = sc;
            }
            continue;
        }
        int s = j - 1;
        const float* ar = g_a  + (size_t)(b*Sn + s)*Dn;
        const float* br = g_bm + (size_t)(b*Sn + s)*Dn;
        float4 a0 = *(const float4*)(ar + dlo), b0 = *(const float4*)(br + dlo);
        float4 a1 = *(const float4*)(ar + dhi), b1 = *(const float4*)(br + dhi);
        float x[8];
        x[0]=a0.x+b0.x; x[1]=a0.y+b0.y; x[2]=a0.z+b0.z; x[3]=a0.w+b0.w;
        x[4]=a1.x+b1.x; x[5]=a1.y+b1.y; x[6]=a1.z+b1.z; x[7]=a1.w+b1.w;
        float edot = edge_ln_dot8(x, gg, bbv, ur, lane);
        if (lane < Hn) {
            float sc = g_qs[(b*Nn+0)*Hn + lane] + g_ks[(b*Nn+j)*Hn + lane] + battn
                     + edot + ub;
            scores[((size_t)(b*Hn + lane)*Nn + 0)*Nn + j] = sc;
        }
    }
}

// ------------------------- main edge tile (i in 1..128) ----------------------
// smem: bT[32*256] qsT[32*8] ksT[32*8] scT[8*1025] naT[1024]
#define SCT_PITCH 1025
#define EDGE_SMEM ((32*256 + 32*8 + 32*8 + 8*SCT_PITCH)*4 + 1024)
__device__ void edge_main(int b, int it, int jt,
                          const float* __restrict__ ln_g, const float* __restrict__ ln_b,
                          float battn, float* __restrict__ scores, char* raw) {
    float* bT  = (float*)raw;
    float* qsT = bT + 32*256;
    float* ksT = qsT + 32*8;
    float* scT = ksT + 32*8;
    unsigned char* naT = (unsigned char*)(scT + 8*SCT_PITCH);

    int tid = threadIdx.x, warp = tid >> 5, lane = tid & 31;

    for (int idx = tid; idx < 32*64; idx += 256) {
        int row = idx >> 6;
        int c4  = (idx & 63) * 4;
        int j = jt*32 + row;
        float4 bv = make_float4(0.f,0.f,0.f,0.f);
        if (j >= 1 && j <= 128)
            bv = *(const float4*)&g_bm[(size_t)(b*Sn + j - 1)*Dn + c4];
        *(float4*)&bT[row*256 + c4] = bv;
    }
    {
        int r = tid >> 3, h = tid & 7;
        int i = 1 + it*32 + r;
        qsT[tid] = g_qs[(size_t)(b*Nn + i)*Hn + h];
        int j = jt*32 + r;
        ksT[tid] = (j <= 128) ? g_ks[(size_t)(b*Nn + j)*Hn + h] : 0.f;
    }
    for (int idx = tid; idx < 1024; idx += 256) {
        int ei = idx >> 5, ej = idx & 31;
        int j = jt*32 + ej;
        int i = 1 + it*32 + ei;
        naT[idx] = (j >= 1 && j <= 128) ? g_na[(size_t)(b*Nn + i)*Nn + j] : 0;
    }

    float gg[8], bbv[8], ur[8][8];
    edge_preload(lane, ln_g, ln_b, gg, bbv, ur);
    float ub = (lane < Hn) ? g_ub[lane] : 0.f;
    __syncthreads();

    #pragma unroll
    for (int eib = 0; eib < 4; eib++) {
        int ei = warp + eib*8;                   // 0..31
        const float* ar = g_a + (size_t)(b*Sn + it*32 + ei)*Dn;
        float4 a0 = *(const float4*)(ar + lane*4);
        float4 a1 = *(const float4*)(ar + 128 + lane*4);
        for (int ej = 0; ej < 32; ej++) {
            int j = jt*32 + ej;
            if (j > 128) continue;
            int slot = ei*32 + ej;
            unsigned char mk = naT[slot];
            float edot = 0.f;
            if (mk) {
                const float* brow = bT + ej*256;
                float4 b0 = *(const float4*)(brow + lane*4);
                float4 b1 = *(const float4*)(brow + 128 + lane*4);
                float x[8];
                x[0]=a0.x+b0.x; x[1]=a0.y+b0.y; x[2]=a0.z+b0.z; x[3]=a0.w+b0.w;
                x[4]=a1.x+b1.x; x[5]=a1.y+b1.y; x[6]=a1.z+b1.z; x[7]=a1.w+b1.w;
                edot = edge_ln_dot8(x, gg, bbv, ur, lane);
            }
            if (lane < Hn) {
                float sc = qsT[ei*8 + lane] + ksT[ej*8 + lane] + battn;
                sc = mk ? (sc + edot + ub) : (sc - NEG_BIG);
                scT[lane*SCT_PITCH + slot] = sc;
            }
        }
    }
    __syncthreads();
    for (int idx = tid; idx < 8192; idx += 256) {
        int h    = idx >> 10;
        int slot = idx & 1023;
        int ei   = slot >> 5;
        int ej   = slot & 31;
        int j = jt*32 + ej;
        if (j <= 128) {
            int i = 1 + it*32 + ei;
            scores[((size_t)(b*Hn + h)*Nn + i)*Nn + j] = scT[h*SCT_PITCH + slot];
        }
    }
}

// ========================= phase mega-kernels ================================

// P0: Wa GEMM (16) | Wb GEMM (16) | v GEMM (68) | na (128) | fold (12) | bias (1) = 241
__global__ void __launch_bounds__(256)
mega0_kernel(const float* __restrict__ W_gt, const float* __restrict__ W_e1,
             const float* __restrict__ b_gt, const float* __restrict__ b_e1,
             const float* __restrict__ nv,   const float* __restrict__ W_v, const float* __restrict__ b_v,
             const float* __restrict__ W_q,  const float* __restrict__ b_q,
             const float* __restrict__ W_k,  const float* __restrict__ b_k,
             const float* __restrict__ We2,  const float* __restrict__ be2,
             const float* __restrict__ wattn) {
    extern __shared__ char raw[];
    int id = blockIdx.x;
    if (id < 16)  { gemm_tile(W_gt, W_e1, nullptr, g_wa, Dn, (id>>2)*TM, (id&3)*TN, raw); return; }
    id -= 16;
    if (id < 16)  { gemm_tile(W_gt, W_e1 + Dn*Dn, nullptr, g_wb, Dn, (id>>2)*TM, (id&3)*TN, raw); return; }
    id -= 16;
    if (id < 68)  { gemm_tile(nv, W_v, b_v, g_v, Bn*Nn, (id>>2)*TM, (id&3)*TN, raw); return; }
    id -= 68;
    if (id < 128) { na_tile(nv, id >> 4, (id >> 2) & 3, id & 3, raw); return; }
    id -= 128;
    if (id < 12)  { fold_block(id, W_q, b_q, W_k, b_k, We2, be2, wattn); return; }
    bias_fold(b_gt, W_e1, b_e1);
}

// P1: a GEMM (64) | b GEMM (64) | qsks (129) = 257
__global__ void __launch_bounds__(256)
mega1_kernel(const float* __restrict__ desc, const float* __restrict__ nv) {
    extern __shared__ char raw[];
    int id = blockIdx.x;
    if (id < 64)  { gemm_tile(desc, g_wa, g_ba, g_a, Bn*Sn, (id>>2)*TM, (id&3)*TN, raw); return; }
    id -= 64;
    if (id < 64)  { gemm_tile(desc, g_wb, g_bb, g_bm, Bn*Sn, (id>>2)*TM, (id&3)*TN, raw); return; }
    id -= 64;
    qsks_tile(nv, id, raw);
}

// P2: edge_row0 (8) | edge_main (160)  = 168 blocks
__global__ void __launch_bounds__(256)
mega3_kernel(const float* __restrict__ ln_g, const float* __restrict__ ln_b,
             const float* __restrict__ p_battn, float* __restrict__ scores) {
    extern __shared__ char raw[];
    float battn = *p_battn;
    int id = blockIdx.x;
    if (id < 8) { edge_row0(id, ln_g, ln_b, battn, scores); return; }
    id -= 8;
    int b = id / 20, rem = id % 20;
    edge_main(b, rem / 5, rem % 5, ln_g, ln_b, battn, scores, raw);
}

// P3: fused softmax + ctx (grid 64 x 16), ONE row per warp (warp 0/by 0: rows 0+128)
__device__ __forceinline__ void softmax_row_load(const float* __restrict__ p, int lane,
                                                 float v[5], float& m) {
    m = NEG_INF;
    #pragma unroll
    for (int k = 0; k < 5; k++) {
        int j = k*32 + lane;
        v[k] = (j < Nn) ? p[j] : NEG_INF;
        m = fmaxf(m, v[k]);
    }
}

__global__ void __launch_bounds__(256) softmax_ctx_kernel(float* __restrict__ scores) {
    __shared__ float vT[Nn][33];
    int bh = blockIdx.x;
    int b = bh >> 3, h = bh & 7;
    int tid = threadIdx.x, warp = tid >> 5, lane = tid & 31;
    for (int idx = tid; idx < Nn*32; idx += 256) {
        int j = idx >> 5, c = idx & 31;
        vT[j][c] = g_v[(size_t)(b*Nn + j)*Dn + h*32 + c];
    }
    __syncthreads();
    const unsigned FULL = 0xffffffffu;
    int start = blockIdx.y*8 + warp;     // 0..127

    for (int i = start; i < Nn; i += 128) {
        float* prow = scores + ((size_t)(b*Hn + h)*Nn + i)*Nn;
        float v[5], m;
        softmax_row_load(prow, lane, v, m);
        #pragma unroll
        for (int off = 16; off; off >>= 1) m = fmaxf(m, __shfl_xor_sync(FULL, m, off));
        float sum = 0.f;
        #pragma unroll
        for (int k = 0; k < 5; k++) {
            int j = k*32 + lane;
            if (j < Nn) { v[k] = expf(v[k] - m); sum += v[k]; }
            else        { v[k] = 0.f; }
        }
        #pragma unroll
        for (int off = 16; off; off >>= 1) sum += __shfl_xor_sync(FULL, sum, off);
        float inv = 1.f / sum;
        #pragma unroll
        for (int k = 0; k < 5; k++) {
            int j = k*32 + lane;
            v[k] *= inv;
            if (j < Nn) prow[j] = v[k];
        }
        // attn @ V with 4 independent accumulator chains
        float acc0 = 0.f, acc1 = 0.f, acc2 = 0.f, acc3 = 0.f;
        #pragma unroll
        for (int jj = 0; jj < 128; jj += 4) {
            float r  = v[jj >> 5];           // same source reg for jj..jj+3
            float a0 = __shfl_sync(FULL, r, (jj+0) & 31);
            float a1 = __shfl_sync(FULL, r, (jj+1) & 31);
            float a2 = __shfl_sync(FULL, r, (jj+2) & 31);
            float a3 = __shfl_sync(FULL, r, (jj+3) & 31);
            acc0 = fmaf(a0, vT[jj+0][lane], acc0);
            acc1 = fmaf(a1, vT[jj+1][lane], acc1);
            acc2 = fmaf(a2, vT[jj+2][lane], acc2);
            acc3 = fmaf(a3, vT[jj+3][lane], acc3);
        }
        float aLast = __shfl_sync(FULL, v[4], 0);
        acc0 = fmaf(aLast, vT[128][lane], acc0);
        g_ctx[(size_t)(b*Nn + i)*Dn + h*32 + lane] = (acc0 + acc1) + (acc2 + acc3);
    }
}

// P4: ctx -> out GEMM (68 blocks)
__global__ void __launch_bounds__(256)
gemm_out_kernel(const float* __restrict__ W_o, const float* __restrict__ b_o,
                float* __restrict__ outp) {
    extern __shared__ char raw[];
    int id = blockIdx.x;
    gemm_tile(g_ctx, W_o, b_o, outp, Bn*Nn, (id>>2)*TM, (id&3)*TN, raw);
}

// ------------------------- launch --------------------------------------------
extern "C" void kernel_launch(void* const* d_in, const int* in_sizes, int n_in,
                              void* d_out, int out_size) {
    const float* desc   = (const float*)d_in[0];
    const float* nv     = (const float*)d_in[1];
    const float* W_gt   = (const float*)d_in[2];
    const float* b_gt   = (const float*)d_in[3];
    // d_in[4] = topo_bias: irrelevant to forward value (sigmoid>0 always)
    const float* W_q    = (const float*)d_in[5];
    const float* b_q    = (const float*)d_in[6];
    const float* W_k    = (const float*)d_in[7];
    const float* b_k    = (const float*)d_in[8];
    const float* W_v    = (const float*)d_in[9];
    const float* b_v    = (const float*)d_in[10];
    const float* W_e1   = (const float*)d_in[11];
    const float* b_e1   = (const float*)d_in[12];
    const float* ln_g   = (const float*)d_in[13];
    const float* ln_b   = (const float*)d_in[14];
    const float* W_e2   = (const float*)d_in[15];
    const float* b_e2   = (const float*)d_in[16];
    const float* w_attn = (const float*)d_in[17];
    const float* b_attn = (const float*)d_in[18];
    const float* W_o    = (const float*)d_in[19];
    const float* b_o    = (const float*)d_in[20];

    float* outp   = (float*)d_out;
    float* scores = outp + Bn*Nn*Dn;     // attn region of output, used in place

    cudaFuncSetAttribute(mega0_kernel, cudaFuncAttributeMaxDynamicSharedMemorySize, NA_SMEM);
    cudaFuncSetAttribute(mega3_kernel, cudaFuncAttributeMaxDynamicSharedMemorySize, EDGE_SMEM);

    mega0_kernel<<<241, 256, NA_SMEM>>>(W_gt, W_e1, b_gt, b_e1, nv, W_v, b_v,
                                        W_q, b_q, W_k, b_k, W_e2, b_e2, w_attn);
    mega1_kernel<<<257, 256, GEMM_SMEM>>>(desc, nv);
    mega3_kernel<<<168, 256, EDGE_SMEM>>>(ln_g, ln_b, b_attn, scores);
    softmax_ctx_kernel<<<dim3(Bn*Hn, 16), 256>>>(scores);
    gemm_out_kernel<<<68, 256, GEMM_SMEM>>>(W_o, b_o, outp);
}